// round 3
// baseline (speedup 1.0000x reference)
#include <cuda_runtime.h>
#include <cstdint>

// Problem shapes (fixed by setup_inputs)
#define C_      500
#define G_      200
#define F_      500
#define NCLUST_ 10
#define NFRAG_  5000000
#define GF_     (G_ * F_)                 // 100,000
#define CG_     (C_ * G_)                 // 100,000
#define FPAD_   512                       // padded bins per cg (nibble-packed)
#define CNT_WORDS_ (CG_ * (FPAD_ / 8))    // 6,400,000 u32 words (8 nibbles each)

#define U_BLOCKS_    250                  // 2000 warps: one per (k,g)
#define FRAG_BLOCKS_ ((NFRAG_ / 4 + 255) / 256)   // 4883

// Scratch (device globals — statically zero-initialized; k_out re-zeroes g_cnt)
__device__ unsigned int g_cnt[CNT_WORDS_];              // 25.6 MB nibble histogram
__device__ __align__(16) float g_u[NCLUST_ * GF_ + 16]; // 4 MB u table (+pad for f in [500,512))
__device__ float g_S[NCLUST_ * G_];                     // sum_f exp(u) per (k,g)

// ---------------------------------------------------------------------------
// Kernel A: block-specialized.
//   blocks [0, U_BLOCKS_):    build u-table + exp-sums (warp per (k,g))
//   blocks [U_BLOCKS_, ...):  fragment histogram (pure nibble RED)
__global__ void kA(const float* __restrict__ bincounts,
                   const float* __restrict__ baseline,
                   const float* __restrict__ dw,
                   const float* __restrict__ cm,
                   const int*   __restrict__ genes_oi,
                   const int*   __restrict__ cgix,
                   const int*   __restrict__ binix) {
    if (blockIdx.x < U_BLOCKS_) {
        int warp = blockIdx.x * 8 + (threadIdx.x >> 5);   // = k*G_ + g, < 2000
        int lane = threadIdx.x & 31;
        int k = warp / G_;
        int g = warp - k * G_;
        float a  = dw[k];
        float b  = cm[k];
        int   go = genes_oi[g];
        const float* brow = bincounts + (size_t)g  * F_;
        const float* lrow = baseline  + (size_t)go * F_;
        float*       urow = g_u       + (size_t)warp * F_; // k*GF_ + g*F_
        float s = 0.0f;
        #pragma unroll 4
        for (int f = lane; f < F_; f += 32) {
            float u = fmaf(brow[f], a, lrow[f] + b);
            urow[f] = u;
            s += __expf(u);
        }
        #pragma unroll
        for (int o = 16; o; o >>= 1) s += __shfl_xor_sync(0xffffffffu, s, o);
        if (lane == 0) g_S[warp] = s;
    } else {
        unsigned i = (blockIdx.x - U_BLOCKS_) * 256 + threadIdx.x;
        if (i >= NFRAG_ / 4) return;
        int4 cg4 = reinterpret_cast<const int4*>(cgix)[i];
        int4 f4  = reinterpret_cast<const int4*>(binix)[i];
        unsigned b0 = ((unsigned)cg4.x << 9) | (unsigned)f4.x;
        unsigned b1 = ((unsigned)cg4.y << 9) | (unsigned)f4.y;
        unsigned b2 = ((unsigned)cg4.z << 9) | (unsigned)f4.z;
        unsigned b3 = ((unsigned)cg4.w << 9) | (unsigned)f4.w;
        atomicAdd(&g_cnt[b0 >> 3], 1u << ((b0 & 7u) << 2));
        atomicAdd(&g_cnt[b1 >> 3], 1u << ((b1 & 7u) << 2));
        atomicAdd(&g_cnt[b2 >> 3], 1u << ((b2 & 7u) << 2));
        atomicAdd(&g_cnt[b3 >> 3], 1u << ((b3 & 7u) << 2));
    }
}

// ---------------------------------------------------------------------------
// Kernel B: bin sweep. One warp per cg: 64 count words (coalesced), sparse
// coalesced u reads, zero-write-back for the next graph replay.
//   out[cg] = sum_{f: n>0} (n*u - log(n!)) - S[k,g]
__global__ void k_out(const int* __restrict__ labels,
                      float*     __restrict__ out) {
    __shared__ float s_lf[16];                 // s_lf[n] = log(n!)
    if (threadIdx.x < 16) s_lf[threadIdx.x] = lgammaf((float)threadIdx.x + 1.0f);
    __syncthreads();

    int warp = (blockIdx.x * blockDim.x + threadIdx.x) >> 5;
    int lane = threadIdx.x & 31;
    if (warp >= CG_) return;
    int cg = warp;
    int c  = cg / G_;
    int g  = cg - c * G_;
    int k  = labels[c];

    unsigned*    cnt = g_cnt + (size_t)cg * (FPAD_ / 8);            // 64 words
    const float* ut  = g_u + (size_t)k * GF_ + (size_t)g * F_;      // 500 floats (+pad)

    float acc = 0.0f;
    #pragma unroll
    for (int it = 0; it < 2; it++) {
        int w = it * 32 + lane;
        unsigned cw = cnt[w];
        cnt[w] = 0u;                           // reset for next replay
        if (cw) {
            int fb = w * 8;
            float4 uA = *reinterpret_cast<const float4*>(ut + fb);
            float4 uB = *reinterpret_cast<const float4*>(ut + fb + 4);
            unsigned n;
            n =  cw         & 15u; if (n) acc += fmaf((float)n, uA.x, -s_lf[n]);
            n = (cw >> 4)   & 15u; if (n) acc += fmaf((float)n, uA.y, -s_lf[n]);
            n = (cw >> 8)   & 15u; if (n) acc += fmaf((float)n, uA.z, -s_lf[n]);
            n = (cw >> 12)  & 15u; if (n) acc += fmaf((float)n, uA.w, -s_lf[n]);
            n = (cw >> 16)  & 15u; if (n) acc += fmaf((float)n, uB.x, -s_lf[n]);
            n = (cw >> 20)  & 15u; if (n) acc += fmaf((float)n, uB.y, -s_lf[n]);
            n = (cw >> 24)  & 15u; if (n) acc += fmaf((float)n, uB.z, -s_lf[n]);
            n =  cw >> 28;         if (n) acc += fmaf((float)n, uB.w, -s_lf[n]);
        }
    }
    #pragma unroll
    for (int o = 16; o; o >>= 1) acc += __shfl_xor_sync(0xffffffffu, acc, o);
    if (lane == 0) out[cg] = acc - g_S[k * G_ + g];
}

// ---------------------------------------------------------------------------
extern "C" void kernel_launch(void* const* d_in, const int* in_sizes, int n_in,
                              void* d_out, int out_size) {
    const float* bincounts = (const float*)d_in[0];   // (G,F)
    const float* baseline  = (const float*)d_in[1];   // (N_GENES,F)
    const float* dw        = (const float*)d_in[2];   // (N_CLUST,1,1)
    const float* cm        = (const float*)d_in[3];   // (N_CLUST,)
    const int*   genes_oi  = (const int*)d_in[4];     // (G,)
    const int*   labels    = (const int*)d_in[5];     // (C,)
    const int*   cgix      = (const int*)d_in[6];     // (NFRAG,)
    const int*   binix     = (const int*)d_in[7];     // (NFRAG,)
    float*       out       = (float*)d_out;           // (C,G)

    (void)in_sizes; (void)n_in; (void)out_size;

    // A) fused prep + fragment histogram
    kA<<<U_BLOCKS_ + FRAG_BLOCKS_, 256>>>(bincounts, baseline, dw, cm,
                                          genes_oi, cgix, binix);
    // B) bin sweep -> out (also re-zeroes g_cnt)
    {
        int nwarps = CG_;                       // 100000 warps
        k_out<<<(nwarps * 32 + 255) / 256, 256>>>(labels, out);
    }
}